// round 3
// baseline (speedup 1.0000x reference)
#include <cuda_runtime.h>
#include <math.h>
#include <float.h>

#define F_FRAMES 128
#define NPRED    300
#define MTGT     32
#define NCLS     2
#define KID      512

#define HTHREADS 320   // >= NPRED, multiple of 32
#define NWARPS   (HTHREADS/32)

// scratch (no allocations allowed)
__device__ int    g_pred_idx[F_FRAMES * MTGT];
__device__ double g_acc[3];   // [0]=sum |l1|, [1]=sum giou_pair, [2]=sum nll

__global__ void init_kernel() {
    g_acc[0] = 0.0; g_acc[1] = 0.0; g_acc[2] = 0.0;
}

struct XY { float x1, y1, x2, y2, area; };

__device__ __forceinline__ XY to_xyxy(float cx, float cy, float w, float h) {
    XY r;
    r.x1 = cx - 0.5f * w; r.y1 = cy - 0.5f * h;
    r.x2 = cx + 0.5f * w; r.y2 = cy + 0.5f * h;
    r.area = (r.x2 - r.x1) * (r.y2 - r.y1);
    return r;
}

__device__ __forceinline__ float giou_xy(const XY& a, const XY& b) {
    float ltx = fmaxf(a.x1, b.x1), lty = fmaxf(a.y1, b.y1);
    float rbx = fminf(a.x2, b.x2), rby = fminf(a.y2, b.y2);
    float w = fmaxf(rbx - ltx, 0.f), h = fmaxf(rby - lty, 0.f);
    float inter = w * h;
    float uni = a.area + b.area - inter;
    float iou = inter / uni;
    float LTx = fminf(a.x1, b.x1), LTy = fminf(a.y1, b.y1);
    float RBx = fmaxf(a.x2, b.x2), RBy = fmaxf(a.y2, b.y2);
    float W = fmaxf(RBx - LTx, 0.f), H = fmaxf(RBy - LTy, 0.f);
    float ac = W * H;
    return iou - (ac - uni) / ac;
}

__device__ __forceinline__ void warp_argmin(double& v, int& i) {
    #pragma unroll
    for (int off = 16; off > 0; off >>= 1) {
        double ov = __shfl_down_sync(0xffffffffu, v, off);
        int    oi = __shfl_down_sync(0xffffffffu, i, off);
        if (ov < v || (ov == v && oi < i)) { v = ov; i = oi; }
    }
}

// One block per frame: build cost matrix in smem, run Jonker-Volgenant.
__global__ __launch_bounds__(HTHREADS, 1)
void hungarian_kernel(const float* __restrict__ pl,   // [F,N,2]
                      const float* __restrict__ pb,   // [F,N,4]
                      const int*   __restrict__ tlab, // [F,M]
                      const float* __restrict__ tbx)  // [F,M,4]
{
    const int f   = blockIdx.x;
    const int tid = threadIdx.x;
    const int lane = tid & 31;
    const int wid  = tid >> 5;

    __shared__ float  s_cost[MTGT * NPRED];       // [t][j]  38400 B
    __shared__ double s_v[NPRED + 1];
    __shared__ double s_minv[NPRED + 1];
    __shared__ double s_u[MTGT + 1];
    __shared__ int    s_way[NPRED + 1];
    __shared__ int    s_p[NPRED + 1];
    __shared__ int    s_used[NPRED + 1];
    __shared__ XY     s_tb[MTGT];
    __shared__ int    s_tl[MTGT];
    __shared__ double s_redv[NWARPS];
    __shared__ int    s_redi[NWARPS];
    __shared__ int    s_j0, s_i0, s_j1;
    __shared__ double s_delta;

    // ---- load targets ----
    if (tid < MTGT) {
        const float* t = tbx + (size_t)(f * MTGT + tid) * 4;
        s_tb[tid] = to_xyxy(t[0], t[1], t[2], t[3]);
        s_tl[tid] = tlab[f * MTGT + tid];
    }
    if (tid <= NPRED) { s_v[tid] = 0.0; s_p[tid] = 0; }
    if (tid <= MTGT)  s_u[tid] = 0.0;
    __syncthreads();

    // ---- build cost matrix: thread j handles pred j, loops over 32 targets ----
    if (tid < NPRED) {
        const float* lg = pl + (size_t)(f * NPRED + tid) * NCLS;
        float x0 = lg[0], x1 = lg[1];
        float mx = fmaxf(x0, x1);
        float e0 = expf(x0 - mx), e1 = expf(x1 - mx);
        float inv = 1.0f / (e0 + e1);
        float prob[2] = { e0 * inv, e1 * inv };

        const float* bp = pb + (size_t)(f * NPRED + tid) * 4;
        float cx = bp[0], cy = bp[1], bw = bp[2], bh = bp[3];
        XY a = to_xyxy(cx, cy, bw, bh);

        #pragma unroll 4
        for (int t = 0; t < MTGT; t++) {
            const float* tb4 = tbx + (size_t)(f * MTGT + t) * 4;
            float l1 = fabsf(cx - tb4[0]) + fabsf(cy - tb4[1])
                     + fabsf(bw - tb4[2]) + fabsf(bh - tb4[3]);
            float g  = giou_xy(a, s_tb[t]);
            float cc = -prob[s_tl[t]];
            s_cost[t * NPRED + tid] = 2.0f * cc + 5.0f * l1 + 2.0f * (-g);
        }
    }
    __syncthreads();

    // ---- JV shortest augmenting path, rows i = 1..MTGT ----
    for (int i = 1; i <= MTGT; i++) {
        if (tid <= NPRED) { s_minv[tid] = DBL_MAX; s_used[tid] = 0; }
        if (tid == 0) { s_p[0] = i; s_j0 = 0; }
        __syncthreads();

        while (true) {
            if (tid == 0) { s_used[s_j0] = 1; s_i0 = s_p[s_j0]; }
            __syncthreads();
            const int i0 = s_i0;
            const int j0 = s_j0;

            double val = DBL_MAX; int jj = 0x7fffffff;
            if (tid < NPRED) {
                const int j = tid + 1;
                if (!s_used[j]) {
                    double cur = (double)s_cost[(i0 - 1) * NPRED + tid]
                               - s_u[i0] - s_v[j];
                    if (cur < s_minv[j]) { s_minv[j] = cur; s_way[j] = j0; }
                    val = s_minv[j]; jj = j;
                }
            }
            warp_argmin(val, jj);
            if (lane == 0) { s_redv[wid] = val; s_redi[wid] = jj; }
            __syncthreads();
            if (wid == 0) {
                double v2 = (lane < NWARPS) ? s_redv[lane] : DBL_MAX;
                int    i2 = (lane < NWARPS) ? s_redi[lane] : 0x7fffffff;
                warp_argmin(v2, i2);
                if (lane == 0) { s_delta = v2; s_j1 = i2; }
            }
            __syncthreads();
            const double delta = s_delta;
            const int j1 = s_j1;

            if (tid <= NPRED) {
                if (s_used[tid]) { s_u[s_p[tid]] += delta; s_v[tid] -= delta; }
                else if (tid > 0) s_minv[tid] -= delta;
            }
            if (tid == 0) s_j0 = j1;
            __syncthreads();
            if (s_p[j1] == 0) break;
        }

        if (tid == 0) {
            int j0 = s_j0;
            while (j0) { int j1 = s_way[j0]; s_p[j0] = s_p[j1]; j0 = j1; }
        }
        __syncthreads();
    }

    // ---- emit col4row: pred index for each target row ----
    if (tid < NPRED) {
        const int j = tid + 1;
        const int r = s_p[j];
        if (r > 0) g_pred_idx[f * MTGT + (r - 1)] = j - 1;
    }
}

// One block per frame: l1, giou_pair, id cross-entropy.
__global__ __launch_bounds__(256, 2)
void loss_kernel(const float* __restrict__ pb,    // [F,N,4]
                 const float* __restrict__ il,    // [F,N,512]
                 const float* __restrict__ tbx,   // [F,M,4]
                 const int*   __restrict__ tids)  // [F,M]
{
    const int f    = blockIdx.x;
    const int tid  = threadIdx.x;
    const int lane = tid & 31;
    const int wid  = tid >> 5;   // 8 warps

    __shared__ double s_l1, s_g, s_id;
    if (tid == 0) { s_l1 = 0.0; s_g = 0.0; s_id = 0.0; }
    __syncthreads();

    // ---- L1 + pair GIoU: one thread per target ----
    if (tid < MTGT) {
        const int idx = g_pred_idx[f * MTGT + tid];
        const float* bp = pb  + (size_t)(f * NPRED + idx) * 4;
        const float* bt = tbx + (size_t)(f * MTGT + tid) * 4;
        float l1 = fabsf(bp[0] - bt[0]) + fabsf(bp[1] - bt[1])
                 + fabsf(bp[2] - bt[2]) + fabsf(bp[3] - bt[3]);
        XY a = to_xyxy(bp[0], bp[1], bp[2], bp[3]);
        XY b = to_xyxy(bt[0], bt[1], bt[2], bt[3]);
        float g = giou_xy(a, b);
        atomicAdd(&s_l1, (double)l1);
        atomicAdd(&s_g,  (double)g);
    }

    // ---- ID cross-entropy: each warp handles 4 rows of K=512 ----
    double id_part = 0.0;
    for (int t = wid; t < MTGT; t += 8) {
        const int idx = g_pred_idx[f * MTGT + t];
        const float* row = il + (size_t)(f * NPRED + idx) * KID;
        float xv[16];
        float mx = -FLT_MAX;
        #pragma unroll
        for (int k = 0; k < 16; k++) {
            xv[k] = row[lane + 32 * k];
            mx = fmaxf(mx, xv[k]);
        }
        #pragma unroll
        for (int off = 16; off > 0; off >>= 1)
            mx = fmaxf(mx, __shfl_xor_sync(0xffffffffu, mx, off));
        float se = 0.f;
        #pragma unroll
        for (int k = 0; k < 16; k++) se += __expf(xv[k] - mx);
        #pragma unroll
        for (int off = 16; off > 0; off >>= 1)
            se += __shfl_xor_sync(0xffffffffu, se, off);
        if (lane == 0) {
            float lse = logf(se) + mx;
            int tg = tids[f * MTGT + t];
            float nll = lse - row[tg];
            id_part += (double)nll;
        }
    }
    if (lane == 0 && id_part != 0.0) atomicAdd(&s_id, id_part);

    __syncthreads();
    if (tid == 0) {
        atomicAdd(&g_acc[0], s_l1);
        atomicAdd(&g_acc[1], s_g);
        atomicAdd(&g_acc[2], s_id);
    }
}

__global__ void finalize_kernel(float* __restrict__ out) {
    const double FM = (double)(F_FRAMES * MTGT);
    double l1   = g_acc[0] / (FM * 4.0);
    double giou = 1.0 - g_acc[1] / FM;
    double idl  = g_acc[2] / FM;
    double loss = 5.0 * l1 + 2.0 * giou + 1.0 * idl;
    out[0] = (float)loss;
    out[1] = 0.0f;
    out[2] = (float)l1;
    out[3] = (float)giou;
    out[4] = (float)idl;
}

extern "C" void kernel_launch(void* const* d_in, const int* in_sizes, int n_in,
                              void* d_out, int out_size) {
    const float* pred_logits   = (const float*)d_in[0];  // [8,16,300,2]
    const float* pred_boxes    = (const float*)d_in[1];  // [8,16,300,4]
    const float* id_logits     = (const float*)d_in[2];  // [8,16,300,512]
    const int*   target_labels = (const int*)  d_in[3];  // [128,32]
    const float* target_boxes  = (const float*)d_in[4];  // [128,32,4]
    const int*   target_ids    = (const int*)  d_in[5];  // [128,32]
    float* out = (float*)d_out;

    init_kernel<<<1, 1>>>();
    hungarian_kernel<<<F_FRAMES, HTHREADS>>>(pred_logits, pred_boxes,
                                             target_labels, target_boxes);
    loss_kernel<<<F_FRAMES, 256>>>(pred_boxes, id_logits,
                                   target_boxes, target_ids);
    finalize_kernel<<<1, 1>>>(out);
}